// round 13
// baseline (speedup 1.0000x reference)
#include <cuda_runtime.h>
#include <cstdint>

// Problem constants
#define BQ   8
#define HQ   16
#define NQ   8192
#define HD   64
#define NJ   20
#define TILE 256         // query positions per block
#define HALO 128
#define HROWS (TILE + HALO)   // 384
#define PPG  2           // positions per 8-lane group
#define NE   25          // distinct smem band rows per pair

typedef unsigned long long ull;

static __device__ __forceinline__ ull pk2(float lo, float hi) {
    ull r;
    asm("mov.b64 %0, {%1,%2};" : "=l"(r) : "f"(lo), "f"(hi));
    return r;
}
static __device__ __forceinline__ ull f2fma(ull a, ull b, ull c) {
    ull r;
    asm("fma.rn.f32x2 %0, %1, %2, %3;" : "=l"(r) : "l"(a), "l"(b), "l"(c));
    return r;
}
static __device__ __forceinline__ ull f2mul(ull a, ull b) {
    ull r;
    asm("mul.rn.f32x2 %0, %1, %2;" : "=l"(r) : "l"(a), "l"(b));
    return r;
}
static __device__ __forceinline__ float f2hadd(ull a) {
    float lo, hi;
    asm("mov.b64 {%0,%1}, %2;" : "=f"(lo), "=f"(hi) : "l"(a));
    return lo + hi;
}
static __device__ __forceinline__ float dot8(const ulonglong2& A0, const ulonglong2& A1,
                                             const ulonglong2& B0, const ulonglong2& B1) {
    ull t =
        f2fma(A0.x, B0.x, f2fma(A0.y, B0.y, f2fma(A1.x, B1.x, f2fma(A1.y, B1.y, 0ull))));
    return f2hadd(t);
}
static __device__ __forceinline__ float bfly8(float p) {
    p += __shfl_xor_sync(0xffffffffu, p, 1);
    p += __shfl_xor_sync(0xffffffffu, p, 2);
    p += __shfl_xor_sync(0xffffffffu, p, 4);
    return p;
}

__device__ __forceinline__ constexpr int offs(int j) {
    constexpr int O[NJ] = {1,2,3,4,5,6,7,8,9,11,13,15,16,23,32,64,128,256,512,1024};
    return O[j];
}
__device__ __forceinline__ constexpr int erow(int i) {
    constexpr int E[NE] = {0,1,2,3,4,5,6,7,8,9,10,11,12,13,14,15,16,
                           22,23, 31,32, 63,64, 127,128};
    return E[i];
}
__device__ __forceinline__ constexpr int jof(int d) {
    switch (d) {
        case 1: return 0;  case 2: return 1;  case 3: return 2;  case 4: return 3;
        case 5: return 4;  case 6: return 5;  case 7: return 6;  case 8: return 7;
        case 9: return 8;  case 11: return 9; case 13: return 10; case 15: return 11;
        case 16: return 12; case 23: return 13; case 32: return 14; case 64: return 15;
        case 128: return 16;
        default: return -1;
    }
}

#define SK_FLOATS  (HROWS * HD)      // 24576
#define SSE_FLOATS (NJ * HD)         // 1280
#define SMEM_FLOATS (2 * SK_FLOATS + SSE_FLOATS + 32)
#define SMEM_BYTES  (SMEM_FLOATS * 4)   // ~202 KB

__global__ void __launch_bounds__(1024, 1)
dsqg_attn_kernel(const float* __restrict__ q,
                 const float* __restrict__ k,
                 const float* __restrict__ v,
                 const float* __restrict__ pb,   // [NJ, HQ]
                 const float* __restrict__ se,   // [NJ, HD]
                 float* __restrict__ out)
{
    extern __shared__ float sm[];
    float* sk  = sm;                       // [HROWS][HD]
    float* sv  = sm + SK_FLOATS;           // [HROWS][HD]
    float* sse = sm + 2 * SK_FLOATS;       // [NJ][HD]
    float* spb = sse + SSE_FLOATS;         // [NJ]

    const int bh   = blockIdx.y;
    const int h    = bh & (HQ - 1);
    const int n0   = blockIdx.x * TILE;
    const int base = bh * (NQ * HD);
    const int tid  = threadIdx.x;

    // ---- cooperative fills ----
    {
        const int total4 = SK_FLOATS / 4;   // 6144 per array
        const int e0 = (n0 - HALO) * HD;
        #pragma unroll 2
        for (int i = tid; i < total4; i += 1024) {
            int ge = e0 + i * 4;
            float4 kv = make_float4(0.f, 0.f, 0.f, 0.f);
            float4 vv = kv;
            if (ge >= 0) {
                kv = *(const float4*)(k + base + ge);
                vv = *(const float4*)(v + base + ge);
            }
            ((float4*)sk)[i] = kv;
            ((float4*)sv)[i] = vv;
        }
        for (int i = tid; i < SSE_FLOATS / 4; i += 1024)
            ((float4*)sse)[i] = ((const float4*)se)[i];
        if (tid < NJ) spb[tid] = pb[tid * HQ + h];
    }
    __syncthreads();

    const int g  = tid >> 3;        // 0..127
    const int l  = tid & 7;
    const int c0 = l * 4;
    const int c1 = 32 + l * 4;
    const int n  = n0 + g * PPG;
    const int liBase = g * PPG + HALO;   // halo row of position n
    const float NEG_INF = __int_as_float(0xff800000);

    // Q for 2 positions
    ulonglong2 Q0[PPG], Q1[PPG];
    #pragma unroll
    for (int p = 0; p < PPG; ++p) {
        const float* qr = q + base + (n + p) * HD;
        Q0[p] = *(const ulonglong2*)(qr + c0);
        Q1[p] = *(const ulonglong2*)(qr + c1);
    }

    // ---- pass 1a: s[p][j] = (q.se_j)/8 + pb[j]  (j-outer: se reads broadcast) ----
    float s[PPG][NJ];
    #pragma unroll
    for (int j = 0; j < NJ; ++j) {
        const float* sr = sse + j * HD;
        const ulonglong2 S0 = *(const ulonglong2*)(sr + c0);   // 1-wf broadcast
        const ulonglong2 S1 = *(const ulonglong2*)(sr + c1);
        #pragma unroll
        for (int p = 0; p < PPG; ++p) {
            float t = bfly8(dot8(Q0[p], Q1[p], S0, S1));
            s[p][j] = fmaf(t, 0.125f, spb[j]);
        }
    }

    // ---- pass 1b: band rows from smem, each k row shared by the pair ----
    #pragma unroll
    for (int ei = 0; ei < NE; ++ei) {
        const int e = erow(ei);
        const float* kr = sk + (liBase - e) * HD;
        const ulonglong2 K0 = *(const ulonglong2*)(kr + c0);
        const ulonglong2 K1 = *(const ulonglong2*)(kr + c1);
        #pragma unroll
        for (int p = 0; p < PPG; ++p) {
            const int j = jof(e + p);      // compile-time
            if (j >= 0) {
                float t = bfly8(dot8(Q0[p], Q1[p], K0, K1));
                s[p][j] = ((n + p) >= (e + p)) ? fmaf(t, 0.125f, s[p][j]) : NEG_INF;
            }
        }
    }

    // ---- pass 1c: far offsets from global (clamped loads, uniform shuffles) ----
    #pragma unroll
    for (int jf = 0; jf < 3; ++jf) {
        const int d = (jf == 0) ? 256 : ((jf == 1) ? 512 : 1024);
        const int j = 17 + jf;
        #pragma unroll
        for (int p = 0; p < PPG; ++p) {
            const bool valid = (n + p) >= d;
            const int idx = valid ? (n + p - d) : 0;
            const float* kr = k + base + idx * HD;
            const ulonglong2 K0 = *(const ulonglong2*)(kr + c0);
            const ulonglong2 K1 = *(const ulonglong2*)(kr + c1);
            float t = bfly8(dot8(Q0[p], Q1[p], K0, K1));
            s[p][j] = valid ? fmaf(t, 0.125f, s[p][j]) : NEG_INF;
        }
    }

    // ---- softmax (unnormalized weights; normalize at store) ----
    float inv[PPG];
    #pragma unroll
    for (int p = 0; p < PPG; ++p) {
        float m = s[p][0];
        #pragma unroll
        for (int j = 1; j < NJ; ++j) m = fmaxf(m, s[p][j]);
        if ((n + p) == 0) m = 0.f;
        float den = 0.f;
        #pragma unroll
        for (int j = 0; j < NJ; ++j) {
            s[p][j] = __expf(s[p][j] - m);
            den += s[p][j];
        }
        inv[p] = __frcp_rn(fmaxf(den, 1e-30f));
    }

    // ---- pass 2: weighted V with the same row reuse ----
    ulonglong2 A0[PPG], A1[PPG];
    #pragma unroll
    for (int p = 0; p < PPG; ++p) {
        A0[p].x = A0[p].y = A1[p].x = A1[p].y = 0ull;
    }

    #pragma unroll
    for (int ei = 0; ei < NE; ++ei) {
        const int e = erow(ei);
        const float* vr = sv + (liBase - e) * HD;
        const ulonglong2 V0 = *(const ulonglong2*)(vr + c0);
        const ulonglong2 V1 = *(const ulonglong2*)(vr + c1);
        #pragma unroll
        for (int p = 0; p < PPG; ++p) {
            const int j = jof(e + p);
            if (j >= 0) {
                const float w = s[p][j];   // masked positions carry w=0
                const ull w2 = pk2(w, w);
                A0[p].x = f2fma(w2, V0.x, A0[p].x);
                A0[p].y = f2fma(w2, V0.y, A0[p].y);
                A1[p].x = f2fma(w2, V1.x, A1[p].x);
                A1[p].y = f2fma(w2, V1.y, A1[p].y);
            }
        }
    }

    #pragma unroll
    for (int jf = 0; jf < 3; ++jf) {
        const int d = (jf == 0) ? 256 : ((jf == 1) ? 512 : 1024);
        const int j = 17 + jf;
        #pragma unroll
        for (int p = 0; p < PPG; ++p) {
            const bool valid = (n + p) >= d;
            const int idx = valid ? (n + p - d) : 0;
            const float* vr = v + base + idx * HD;
            const ulonglong2 V0 = *(const ulonglong2*)(vr + c0);
            const ulonglong2 V1 = *(const ulonglong2*)(vr + c1);
            const float w = valid ? s[p][j] : 0.f;
            const ull w2 = pk2(w, w);
            A0[p].x = f2fma(w2, V0.x, A0[p].x);
            A0[p].y = f2fma(w2, V0.y, A0[p].y);
            A1[p].x = f2fma(w2, V1.x, A1[p].x);
            A1[p].y = f2fma(w2, V1.y, A1[p].y);
        }
    }

    // ---- normalize + store ----
    #pragma unroll
    for (int p = 0; p < PPG; ++p) {
        const ull iv2 = pk2(inv[p], inv[p]);
        ulonglong2 R0, R1;
        R0.x = f2mul(A0[p].x, iv2);
        R0.y = f2mul(A0[p].y, iv2);
        R1.x = f2mul(A1[p].x, iv2);
        R1.y = f2mul(A1[p].y, iv2);
        float* outr = out + base + (n + p) * HD;
        *(ulonglong2*)(outr + c0) = R0;
        *(ulonglong2*)(outr + c1) = R1;
    }
}

extern "C" void kernel_launch(void* const* d_in, const int* in_sizes, int n_in,
                              void* d_out, int out_size)
{
    const float* q  = (const float*)d_in[0];
    const float* k  = (const float*)d_in[1];
    const float* v  = (const float*)d_in[2];
    const float* pb = (const float*)d_in[3];
    const float* se = (const float*)d_in[4];
    float* out = (float*)d_out;

    cudaFuncSetAttribute(dsqg_attn_kernel,
                         cudaFuncAttributeMaxDynamicSharedMemorySize, SMEM_BYTES);

    dim3 grid(NQ / TILE, BQ * HQ);
    dsqg_attn_kernel<<<grid, 1024, SMEM_BYTES>>>(q, k, v, pb, se, out);
}

// round 15
// speedup vs baseline: 1.1471x; 1.1471x over previous
#include <cuda_runtime.h>
#include <cstdint>

// Problem constants
#define BQ   8
#define HQ   16
#define NQ   8192
#define HD   64
#define NJ   20
#define TILE 256         // query positions per main block
#define HALO 128
#define HROWS (TILE + HALO)   // 384
#define PPG  2           // positions per 8-lane group
#define NE   25          // distinct smem band rows per pair

// 84MB scratch: pre[bh][t4(5)][n][4] = ((q.se_j)/8 + pb[j,h]) quads
__device__ float g_pre[BQ * HQ * 5 * NQ * 4];

// se/pb in constant memory (separate const port; LDC.128 loads)
__constant__ __align__(16) float c_se[NJ * HD];
__constant__ float c_pb[NJ * HQ];

typedef unsigned long long ull;

static __device__ __forceinline__ ull pk2(float lo, float hi) {
    ull r;
    asm("mov.b64 %0, {%1,%2};" : "=l"(r) : "f"(lo), "f"(hi));
    return r;
}
static __device__ __forceinline__ ull f2fma(ull a, ull b, ull c) {
    ull r;
    asm("fma.rn.f32x2 %0, %1, %2, %3;" : "=l"(r) : "l"(a), "l"(b), "l"(c));
    return r;
}
static __device__ __forceinline__ ull f2mul(ull a, ull b) {
    ull r;
    asm("mul.rn.f32x2 %0, %1, %2;" : "=l"(r) : "l"(a), "l"(b));
    return r;
}
static __device__ __forceinline__ float f2hadd(ull a) {
    float lo, hi;
    asm("mov.b64 {%0,%1}, %2;" : "=f"(lo), "=f"(hi) : "l"(a));
    return lo + hi;
}
static __device__ __forceinline__ float dot8(const ulonglong2& A0, const ulonglong2& A1,
                                             const ulonglong2& B0, const ulonglong2& B1) {
    ull t =
        f2fma(A0.x, B0.x, f2fma(A0.y, B0.y, f2fma(A1.x, B1.x, f2fma(A1.y, B1.y, 0ull))));
    return f2hadd(t);
}
static __device__ __forceinline__ float bfly8(float p) {
    p += __shfl_xor_sync(0xffffffffu, p, 1);
    p += __shfl_xor_sync(0xffffffffu, p, 2);
    p += __shfl_xor_sync(0xffffffffu, p, 4);
    return p;
}

static __device__ __forceinline__ uint32_t smem_u32(const void* p) {
    uint32_t a;
    asm("{ .reg .u64 t; cvta.to.shared.u64 t, %1; cvt.u32.u64 %0, t; }"
        : "=r"(a) : "l"(p));
    return a;
}
static __device__ __forceinline__ void bulk_g2s(uint32_t dst, const void* src,
                                                uint32_t bytes, uint32_t bar) {
    asm volatile(
        "cp.async.bulk.shared::cluster.global.mbarrier::complete_tx::bytes "
        "[%0], [%1], %2, [%3];"
        :: "r"(dst), "l"(src), "r"(bytes), "r"(bar) : "memory");
}
static __device__ __forceinline__ void mbar_init(uint32_t bar, uint32_t cnt) {
    asm volatile("mbarrier.init.shared.b64 [%0], %1;" :: "r"(bar), "r"(cnt) : "memory");
}
static __device__ __forceinline__ void mbar_expect(uint32_t bar, uint32_t tx) {
    asm volatile("mbarrier.arrive.expect_tx.shared.b64 _, [%0], %1;"
                 :: "r"(bar), "r"(tx) : "memory");
}
static __device__ __forceinline__ void mbar_wait(uint32_t bar, uint32_t parity) {
    uint32_t done;
    asm volatile(
        "{\n\t.reg .pred p;\n\t"
        "mbarrier.try_wait.parity.acquire.cta.shared::cta.b64 p, [%1], %2;\n\t"
        "selp.b32 %0, 1, 0, p;\n\t}"
        : "=r"(done) : "r"(bar), "r"(parity) : "memory");
    if (!done) {
        asm volatile(
            "{\n\t.reg .pred P1;\n\t"
            "W_%=:\n\t"
            "mbarrier.try_wait.parity.acquire.cta.shared::cta.b64 P1, [%0], %1, 0x989680;\n\t"
            "@P1 bra.uni D_%=;\n\t"
            "bra.uni W_%=;\n\t"
            "D_%=:\n\t}"
            :: "r"(bar), "r"(parity) : "memory");
    }
}

__device__ __forceinline__ constexpr int offs(int j) {
    constexpr int O[NJ] = {1,2,3,4,5,6,7,8,9,11,13,15,16,23,32,64,128,256,512,1024};
    return O[j];
}
__device__ __forceinline__ constexpr int erow(int i) {
    constexpr int E[NE] = {0,1,2,3,4,5,6,7,8,9,10,11,12,13,14,15,16,
                           22,23, 31,32, 63,64, 127,128};
    return E[i];
}
__device__ __forceinline__ constexpr int jof(int d) {
    switch (d) {
        case 1: return 0;  case 2: return 1;  case 3: return 2;  case 4: return 3;
        case 5: return 4;  case 6: return 5;  case 7: return 6;  case 8: return 7;
        case 9: return 8;  case 11: return 9; case 13: return 10; case 15: return 11;
        case 16: return 12; case 23: return 13; case 32: return 14; case 64: return 15;
        case 128: return 16;
        default: return -1;
    }
}

#define SK_FLOATS  (HROWS * HD)      // 24576
#define SMEM_FLOATS (2 * SK_FLOATS)
#define SMEM_BYTES  (SMEM_FLOATS * 4)   // 196608

// ============ Kernel A: pre = (q . se_j)/8 + pb[j,h] =============
#define PRE_THREADS 256
#define PRE_TILE    256
#define QROW_PAD    68
#define PRE_SMEM_BYTES (PRE_TILE * QROW_PAD * 4)

__global__ void __launch_bounds__(PRE_THREADS)
dsqg_pre_kernel(const float* __restrict__ q)
{
    extern __shared__ float psmf[];
    float* srow = psmf;                         // [PRE_TILE][QROW_PAD]

    const int bh   = blockIdx.y;
    const int h    = bh & (HQ - 1);
    const int n0   = blockIdx.x * PRE_TILE;
    const int tid  = threadIdx.x;
    const int base = (bh * NQ + n0) * HD;

    // stage q rows (coalesced LDG.128 -> conflict-free STS.128)
    for (int i = tid; i < PRE_TILE * 16; i += PRE_THREADS) {
        const int row = i >> 4;
        const int u   = i & 15;
        *(float4*)(srow + row * QROW_PAD + u * 4) =
            *(const float4*)(q + base + row * HD + u * 4);
    }
    __syncthreads();

    ull acc[NJ];
    #pragma unroll
    for (int j = 0; j < NJ; ++j) acc[j] = 0ull;

    const float* myrow = srow + tid * QROW_PAD;
    #pragma unroll 4
    for (int u = 0; u < 16; ++u) {
        const ulonglong2 Qu = *(const ulonglong2*)(myrow + u * 4);   // stride-68, conflict-free
        #pragma unroll
        for (int j = 0; j < NJ; ++j) {
            const ulonglong2 cse = *(const ulonglong2*)(c_se + j * HD + u * 4);  // LDC.128
            acc[j] = f2fma(Qu.x, cse.x, f2fma(Qu.y, cse.y, acc[j]));
        }
    }

    float sc[NJ];
    #pragma unroll
    for (int j = 0; j < NJ; ++j)
        sc[j] = fmaf(f2hadd(acc[j]), 0.125f, c_pb[j * HQ + h]);

    const int n = n0 + tid;
    #pragma unroll
    for (int t4 = 0; t4 < 5; ++t4) {
        *(float4*)(g_pre + ((bh * 5 + t4) * NQ + n) * 4) =
            make_float4(sc[4*t4], sc[4*t4+1], sc[4*t4+2], sc[4*t4+3]);
    }
}

// ======================= Kernel B: main attention ==========================
__global__ void __launch_bounds__(1024, 1)
dsqg_attn_kernel(const float* __restrict__ q,
                 const float* __restrict__ k,
                 const float* __restrict__ v,
                 float* __restrict__ out)
{
    extern __shared__ float sm[];
    float* sk = sm;                  // [HROWS][HD]
    float* sv = sm + SK_FLOATS;      // [HROWS][HD]
    __shared__ __align__(8) ull mbar_store;

    const int bh   = blockIdx.y;
    const int n0   = blockIdx.x * TILE;
    const int base = bh * (NQ * HD);
    const int tid  = threadIdx.x;
    const uint32_t bar = smem_u32(&mbar_store);

    // ---- TMA bulk fills (k,v halo is one contiguous range per array) ----
    if (tid == 0) mbar_init(bar, 1);
    __syncthreads();
    if (tid == 0) {
        int startRow = n0 - HALO;
        int smoff = 0;
        int rows = HROWS;
        if (startRow < 0) { smoff = -startRow; rows = HROWS - smoff; startRow = 0; }
        const uint32_t bytes = (uint32_t)rows * HD * 4u;
        mbar_expect(bar, 2u * bytes);
        bulk_g2s(smem_u32(sk) + (uint32_t)smoff * HD * 4u,
                 k + base + startRow * HD, bytes, bar);
        bulk_g2s(smem_u32(sv) + (uint32_t)smoff * HD * 4u,
                 v + base + startRow * HD, bytes, bar);
    }
    // zero the pad rows (only first tile of each bh slice)
    if (blockIdx.x == 0) {
        for (int i = tid; i < (HALO * HD) / 4; i += 1024) {
            ((float4*)sk)[i] = make_float4(0.f, 0.f, 0.f, 0.f);
            ((float4*)sv)[i] = make_float4(0.f, 0.f, 0.f, 0.f);
        }
    }

    const int g  = tid >> 3;        // 0..127
    const int l  = tid & 7;
    const int c0 = l * 4;
    const int c1 = 32 + l * 4;
    const int n  = n0 + g * PPG;
    const int liBase = g * PPG + HALO;   // halo row of position n
    const float NEG_INF = __int_as_float(0xff800000);

    // Q for 2 positions (global, independent of smem fill)
    ulonglong2 Q0[PPG], Q1[PPG];
    #pragma unroll
    for (int p = 0; p < PPG; ++p) {
        const float* qr = q + base + (n + p) * HD;
        Q0[p] = *(const ulonglong2*)(qr + c0);
        Q1[p] = *(const ulonglong2*)(qr + c1);
    }

    // init scores from precomputed (q.se)/8 + pb  (plane layout)
    float s[PPG][NJ];
    #pragma unroll
    for (int p = 0; p < PPG; ++p) {
        #pragma unroll
        for (int t4 = 0; t4 < 5; ++t4) {
            float4 f = *(const float4*)(g_pre + ((bh * 5 + t4) * NQ + n + p) * 4);
            s[p][t4 * 4 + 0] = f.x;
            s[p][t4 * 4 + 1] = f.y;
            s[p][t4 * 4 + 2] = f.z;
            s[p][t4 * 4 + 3] = f.w;
        }
    }

    __syncthreads();            // covers the zero-pad stores
    mbar_wait(bar, 0);          // TMA data visible (acquire)

    // ---- pass 1: band rows from smem, each k row shared by the pair ----
    #pragma unroll
    for (int ei = 0; ei < NE; ++ei) {
        const int e = erow(ei);
        const float* kr = sk + (liBase - e) * HD;
        const ulonglong2 K0 = *(const ulonglong2*)(kr + c0);
        const ulonglong2 K1 = *(const ulonglong2*)(kr + c1);
        #pragma unroll
        for (int p = 0; p < PPG; ++p) {
            const int j = jof(e + p);      // compile-time
            if (j >= 0) {
                float t = bfly8(dot8(Q0[p], Q1[p], K0, K1));
                s[p][j] = ((n + p) >= (e + p)) ? fmaf(t, 0.125f, s[p][j]) : NEG_INF;
            }
        }
    }

    // ---- far offsets from global (clamped loads, uniform shuffles) ----
    #pragma unroll
    for (int jf = 0; jf < 3; ++jf) {
        const int d = (jf == 0) ? 256 : ((jf == 1) ? 512 : 1024);
        const int j = 17 + jf;
        #pragma unroll
        for (int p = 0; p < PPG; ++p) {
            const bool valid = (n + p) >= d;
            const int idx = valid ? (n + p - d) : 0;
            const float* kr = k + base + idx * HD;
            const ulonglong2 K0 = *(const ulonglong2*)(kr + c0);
            const ulonglong2 K1 = *(const ulonglong2*)(kr + c1);
            float t = bfly8(dot8(Q0[p], Q1[p], K0, K1));
            s[p][j] = valid ? fmaf(t, 0.125f, s[p][j]) : NEG_INF;
        }
    }

    // ---- softmax (unnormalized weights; normalize at store) ----
    float inv[PPG];
    #pragma unroll
    for (int p = 0; p < PPG; ++p) {
        float m = s[p][0];
        #pragma unroll
        for (int j = 1; j < NJ; ++j) m = fmaxf(m, s[p][j]);
        if ((n + p) == 0) m = 0.f;
        float den = 0.f;
        #pragma unroll
        for (int j = 0; j < NJ; ++j) {
            s[p][j] = __expf(s[p][j] - m);
            den += s[p][j];
        }
        inv[p] = __frcp_rn(fmaxf(den, 1e-30f));
    }

    // ---- pass 2: weighted V with the same row reuse ----
    ulonglong2 A0[PPG], A1[PPG];
    #pragma unroll
    for (int p = 0; p < PPG; ++p) {
        A0[p].x = A0[p].y = A1[p].x = A1[p].y = 0ull;
    }

    #pragma unroll
    for (int ei = 0; ei < NE; ++ei) {
        const int e = erow(ei);
        const float* vr = sv + (liBase - e) * HD;
        const ulonglong2 V0 = *(const ulonglong2*)(vr + c0);
        const ulonglong2 V1 = *(const ulonglong2*)(vr + c1);
        #pragma unroll
        for (int p = 0; p < PPG; ++p) {
            const int j = jof(e + p);
            if (j >= 0) {
                const float w = s[p][j];   // masked positions carry w=0
                const ull w2 = pk2(w, w);
                A0[p].x = f2fma(w2, V0.x, A0[p].x);
                A0[p].y = f2fma(w2, V0.y, A0[p].y);
                A1[p].x = f2fma(w2, V1.x, A1[p].x);
                A1[p].y = f2fma(w2, V1.y, A1[p].y);
            }
        }
    }

    #pragma unroll
    for (int jf = 0; jf < 3; ++jf) {
        const int d = (jf == 0) ? 256 : ((jf == 1) ? 512 : 1024);
        const int j = 17 + jf;
        #pragma unroll
        for (int p = 0; p < PPG; ++p) {
            const bool valid = (n + p) >= d;
            const int idx = valid ? (n + p - d) : 0;
            const float* vr = v + base + idx * HD;
            const ulonglong2 V0 = *(const ulonglong2*)(vr + c0);
            const ulonglong2 V1 = *(const ulonglong2*)(vr + c1);
            const float w = valid ? s[p][j] : 0.f;
            const ull w2 = pk2(w, w);
            A0[p].x = f2fma(w2, V0.x, A0[p].x);
            A0[p].y = f2fma(w2, V0.y, A0[p].y);
            A1[p].x = f2fma(w2, V1.x, A1[p].x);
            A1[p].y = f2fma(w2, V1.y, A1[p].y);
        }
    }

    // ---- normalize + store ----
    #pragma unroll
    for (int p = 0; p < PPG; ++p) {
        const ull iv2 = pk2(inv[p], inv[p]);
        ulonglong2 R0, R1;
        R0.x = f2mul(A0[p].x, iv2);
        R0.y = f2mul(A0[p].y, iv2);
        R1.x = f2mul(A1[p].x, iv2);
        R1.y = f2mul(A1[p].y, iv2);
        float* outr = out + base + (n + p) * HD;
        *(ulonglong2*)(outr + c0) = R0;
        *(ulonglong2*)(outr + c1) = R1;
    }
}

extern "C" void kernel_launch(void* const* d_in, const int* in_sizes, int n_in,
                              void* d_out, int out_size)
{
    const float* q  = (const float*)d_in[0];
    const float* k  = (const float*)d_in[1];
    const float* v  = (const float*)d_in[2];
    const float* pb = (const float*)d_in[3];
    const float* se = (const float*)d_in[4];
    float* out = (float*)d_out;

    cudaMemcpyToSymbolAsync(c_se, se, NJ * HD * sizeof(float), 0,
                            cudaMemcpyDeviceToDevice);
    cudaMemcpyToSymbolAsync(c_pb, pb, NJ * HQ * sizeof(float), 0,
                            cudaMemcpyDeviceToDevice);

    cudaFuncSetAttribute(dsqg_pre_kernel,
                         cudaFuncAttributeMaxDynamicSharedMemorySize, PRE_SMEM_BYTES);
    cudaFuncSetAttribute(dsqg_attn_kernel,
                         cudaFuncAttributeMaxDynamicSharedMemorySize, SMEM_BYTES);

    dim3 gridA(NQ / PRE_TILE, BQ * HQ);
    dsqg_pre_kernel<<<gridA, PRE_THREADS, PRE_SMEM_BYTES>>>(q);

    dim3 gridB(NQ / TILE, BQ * HQ);
    dsqg_attn_kernel<<<gridB, 1024, SMEM_BYTES>>>(q, k, v, out);
}

// round 16
// speedup vs baseline: 1.3027x; 1.1356x over previous
#include <cuda_runtime.h>
#include <cstdint>

// Problem constants
#define BQ   8
#define HQ   16
#define NQ   8192
#define HD   64
#define NJ   20
#define TILE 256         // query positions per main block
#define HALO 128
#define HROWS (TILE + HALO)   // 384
#define PPG  2           // positions per 8-lane group
#define NE   25          // distinct smem band rows per pair

// 84MB scratch: pre[bh][t4(5)][n][4] = ((q.se_j)/8 + pb[j,h]) quads
__device__ float g_pre[BQ * HQ * 5 * NQ * 4];

// se/pb in constant memory (separate const port)
__constant__ __align__(16) float c_se[NJ * HD];
__constant__ float c_pb[NJ * HQ];

typedef unsigned long long ull;

static __device__ __forceinline__ ull pk2(float lo, float hi) {
    ull r;
    asm("mov.b64 %0, {%1,%2};" : "=l"(r) : "f"(lo), "f"(hi));
    return r;
}
static __device__ __forceinline__ ull f2fma(ull a, ull b, ull c) {
    ull r;
    asm("fma.rn.f32x2 %0, %1, %2, %3;" : "=l"(r) : "l"(a), "l"(b), "l"(c));
    return r;
}
static __device__ __forceinline__ ull f2mul(ull a, ull b) {
    ull r;
    asm("mul.rn.f32x2 %0, %1, %2;" : "=l"(r) : "l"(a), "l"(b));
    return r;
}
static __device__ __forceinline__ float f2hadd(ull a) {
    float lo, hi;
    asm("mov.b64 {%0,%1}, %2;" : "=f"(lo), "=f"(hi) : "l"(a));
    return lo + hi;
}
static __device__ __forceinline__ float dot8(const ulonglong2& A0, const ulonglong2& A1,
                                             const ulonglong2& B0, const ulonglong2& B1) {
    ull t =
        f2fma(A0.x, B0.x, f2fma(A0.y, B0.y, f2fma(A1.x, B1.x, f2fma(A1.y, B1.y, 0ull))));
    return f2hadd(t);
}
static __device__ __forceinline__ float bfly8(float p) {
    p += __shfl_xor_sync(0xffffffffu, p, 1);
    p += __shfl_xor_sync(0xffffffffu, p, 2);
    p += __shfl_xor_sync(0xffffffffu, p, 4);
    return p;
}

static __device__ __forceinline__ uint32_t smem_u32(const void* p) {
    uint32_t a;
    asm("{ .reg .u64 t; cvta.to.shared.u64 t, %1; cvt.u32.u64 %0, t; }"
        : "=r"(a) : "l"(p));
    return a;
}
static __device__ __forceinline__ void bulk_g2s(uint32_t dst, const void* src,
                                                uint32_t bytes, uint32_t bar) {
    asm volatile(
        "cp.async.bulk.shared::cluster.global.mbarrier::complete_tx::bytes "
        "[%0], [%1], %2, [%3];"
        :: "r"(dst), "l"(src), "r"(bytes), "r"(bar) : "memory");
}
static __device__ __forceinline__ void mbar_init(uint32_t bar, uint32_t cnt) {
    asm volatile("mbarrier.init.shared.b64 [%0], %1;" :: "r"(bar), "r"(cnt) : "memory");
}
static __device__ __forceinline__ void mbar_expect(uint32_t bar, uint32_t tx) {
    asm volatile("mbarrier.arrive.expect_tx.shared.b64 _, [%0], %1;"
                 :: "r"(bar), "r"(tx) : "memory");
}
static __device__ __forceinline__ void mbar_wait(uint32_t bar, uint32_t parity) {
    uint32_t done;
    asm volatile(
        "{\n\t.reg .pred p;\n\t"
        "mbarrier.try_wait.parity.acquire.cta.shared::cta.b64 p, [%1], %2;\n\t"
        "selp.b32 %0, 1, 0, p;\n\t}"
        : "=r"(done) : "r"(bar), "r"(parity) : "memory");
    if (!done) {
        asm volatile(
            "{\n\t.reg .pred P1;\n\t"
            "W_%=:\n\t"
            "mbarrier.try_wait.parity.acquire.cta.shared::cta.b64 P1, [%0], %1, 0x989680;\n\t"
            "@P1 bra.uni D_%=;\n\t"
            "bra.uni W_%=;\n\t"
            "D_%=:\n\t}"
            :: "r"(bar), "r"(parity) : "memory");
    }
}

__device__ __forceinline__ constexpr int offs(int j) {
    constexpr int O[NJ] = {1,2,3,4,5,6,7,8,9,11,13,15,16,23,32,64,128,256,512,1024};
    return O[j];
}
__device__ __forceinline__ constexpr int erow(int i) {
    constexpr int E[NE] = {0,1,2,3,4,5,6,7,8,9,10,11,12,13,14,15,16,
                           22,23, 31,32, 63,64, 127,128};
    return E[i];
}
__device__ __forceinline__ constexpr int jof(int d) {
    switch (d) {
        case 1: return 0;  case 2: return 1;  case 3: return 2;  case 4: return 3;
        case 5: return 4;  case 6: return 5;  case 7: return 6;  case 8: return 7;
        case 9: return 8;  case 11: return 9; case 13: return 10; case 15: return 11;
        case 16: return 12; case 23: return 13; case 32: return 14; case 64: return 15;
        case 128: return 16;
        default: return -1;
    }
}

#define SK_FLOATS  (HROWS * HD)      // 24576
#define SMEM_FLOATS (2 * SK_FLOATS)
#define SMEM_BYTES  (SMEM_FLOATS * 4)   // 196608

// ============ Kernel A: pre = (q . se_j)/8 + pb[j,h] =============
// 2 positions per thread: each LDC.128 of se serves both -> LDC/pos halved.
// Channels processed in 2 phases of 32 to keep smem at 72KB (2 blocks/SM).
#define PRE_THREADS 256
#define PRE_TILE    512
#define QROW_PAD    36      // floats per staged half-row; conflict-free phases
#define PRE_SMEM_BYTES (PRE_TILE * QROW_PAD * 4)

__global__ void __launch_bounds__(PRE_THREADS)
dsqg_pre_kernel(const float* __restrict__ q)
{
    extern __shared__ float psmf[];
    float* srow = psmf;                         // [PRE_TILE][QROW_PAD]

    const int bh   = blockIdx.y;
    const int h    = bh & (HQ - 1);
    const int n0   = blockIdx.x * PRE_TILE;
    const int tid  = threadIdx.x;
    const int base = (bh * NQ + n0) * HD;

    ull accA[NJ], accB[NJ];
    #pragma unroll
    for (int j = 0; j < NJ; ++j) { accA[j] = 0ull; accB[j] = 0ull; }

    #pragma unroll
    for (int ph = 0; ph < 2; ++ph) {
        __syncthreads();     // protect srow from previous phase's readers
        // stage channels [ph*32, ph*32+32) of 512 rows: 4096 float4
        for (int i = tid; i < PRE_TILE * 8; i += PRE_THREADS) {
            const int row = i >> 3;
            const int u   = i & 7;
            *(float4*)(srow + row * QROW_PAD + u * 4) =
                *(const float4*)(q + base + row * HD + ph * 32 + u * 4);
        }
        __syncthreads();

        const float* rowA = srow + tid * QROW_PAD;
        const float* rowB = srow + (tid + 256) * QROW_PAD;
        #pragma unroll 4
        for (int u = 0; u < 8; ++u) {
            const ulonglong2 Qa = *(const ulonglong2*)(rowA + u * 4);
            const ulonglong2 Qb = *(const ulonglong2*)(rowB + u * 4);
            #pragma unroll
            for (int j = 0; j < NJ; ++j) {
                const ulonglong2 cse =
                    *(const ulonglong2*)(c_se + j * HD + ph * 32 + u * 4);  // 1 LDC.128, 2 positions
                accA[j] = f2fma(Qa.x, cse.x, f2fma(Qa.y, cse.y, accA[j]));
                accB[j] = f2fma(Qb.x, cse.x, f2fma(Qb.y, cse.y, accB[j]));
            }
        }
    }

    // epilogue: hadd + scale + bias, coalesced plane stores for both positions
    {
        float sc[NJ];
        #pragma unroll
        for (int j = 0; j < NJ; ++j)
            sc[j] = fmaf(f2hadd(accA[j]), 0.125f, c_pb[j * HQ + h]);
        const int n = n0 + tid;
        #pragma unroll
        for (int t4 = 0; t4 < 5; ++t4)
            *(float4*)(g_pre + ((bh * 5 + t4) * NQ + n) * 4) =
                make_float4(sc[4*t4], sc[4*t4+1], sc[4*t4+2], sc[4*t4+3]);
    }
    {
        float sc[NJ];
        #pragma unroll
        for (int j = 0; j < NJ; ++j)
            sc[j] = fmaf(f2hadd(accB[j]), 0.125f, c_pb[j * HQ + h]);
        const int n = n0 + 256 + tid;
        #pragma unroll
        for (int t4 = 0; t4 < 5; ++t4)
            *(float4*)(g_pre + ((bh * 5 + t4) * NQ + n) * 4) =
                make_float4(sc[4*t4], sc[4*t4+1], sc[4*t4+2], sc[4*t4+3]);
    }
}

// ======================= Kernel B: main attention ==========================
__global__ void __launch_bounds__(1024, 1)
dsqg_attn_kernel(const float* __restrict__ q,
                 const float* __restrict__ k,
                 const float* __restrict__ v,
                 float* __restrict__ out)
{
    extern __shared__ float sm[];
    float* sk = sm;                  // [HROWS][HD]
    float* sv = sm + SK_FLOATS;      // [HROWS][HD]
    __shared__ __align__(8) ull mbar_store;

    const int bh   = blockIdx.y;
    const int n0   = blockIdx.x * TILE;
    const int base = bh * (NQ * HD);
    const int tid  = threadIdx.x;
    const uint32_t bar = smem_u32(&mbar_store);

    // ---- TMA bulk fills (k,v halo is one contiguous range per array) ----
    if (tid == 0) mbar_init(bar, 1);
    __syncthreads();
    if (tid == 0) {
        int startRow = n0 - HALO;
        int smoff = 0;
        int rows = HROWS;
        if (startRow < 0) { smoff = -startRow; rows = HROWS - smoff; startRow = 0; }
        const uint32_t bytes = (uint32_t)rows * HD * 4u;
        mbar_expect(bar, 2u * bytes);
        bulk_g2s(smem_u32(sk) + (uint32_t)smoff * HD * 4u,
                 k + base + startRow * HD, bytes, bar);
        bulk_g2s(smem_u32(sv) + (uint32_t)smoff * HD * 4u,
                 v + base + startRow * HD, bytes, bar);
    }
    // zero the pad rows (only first tile of each bh slice)
    if (blockIdx.x == 0) {
        for (int i = tid; i < (HALO * HD) / 4; i += 1024) {
            ((float4*)sk)[i] = make_float4(0.f, 0.f, 0.f, 0.f);
            ((float4*)sv)[i] = make_float4(0.f, 0.f, 0.f, 0.f);
        }
    }

    const int g  = tid >> 3;        // 0..127
    const int l  = tid & 7;
    const int c0 = l * 4;
    const int c1 = 32 + l * 4;
    const int n  = n0 + g * PPG;
    const int liBase = g * PPG + HALO;   // halo row of position n
    const float NEG_INF = __int_as_float(0xff800000);

    // Q for 2 positions (global, independent of smem fill)
    ulonglong2 Q0[PPG], Q1[PPG];
    #pragma unroll
    for (int p = 0; p < PPG; ++p) {
        const float* qr = q + base + (n + p) * HD;
        Q0[p] = *(const ulonglong2*)(qr + c0);
        Q1[p] = *(const ulonglong2*)(qr + c1);
    }

    // init scores from precomputed (q.se)/8 + pb  (plane layout)
    float s[PPG][NJ];
    #pragma unroll
    for (int p = 0; p < PPG; ++p) {
        #pragma unroll
        for (int t4 = 0; t4 < 5; ++t4) {
            float4 f = *(const float4*)(g_pre + ((bh * 5 + t4) * NQ + n + p) * 4);
            s[p][t4 * 4 + 0] = f.x;
            s[p][t4 * 4 + 1] = f.y;
            s[p][t4 * 4 + 2] = f.z;
            s[p][t4 * 4 + 3] = f.w;
        }
    }

    __syncthreads();            // covers the zero-pad stores
    mbar_wait(bar, 0);          // TMA data visible (acquire)

    // ---- pass 1: band rows from smem, each k row shared by the pair ----
    #pragma unroll
    for (int ei = 0; ei < NE; ++ei) {
        const int e = erow(ei);
        const float* kr = sk + (liBase - e) * HD;
        const ulonglong2 K0 = *(const ulonglong2*)(kr + c0);
        const ulonglong2 K1 = *(const ulonglong2*)(kr + c1);
        #pragma unroll
        for (int p = 0; p < PPG; ++p) {
            const int j = jof(e + p);      // compile-time
            if (j >= 0) {
                float t = bfly8(dot8(Q0[p], Q1[p], K0, K1));
                s[p][j] = ((n + p) >= (e + p)) ? fmaf(t, 0.125f, s[p][j]) : NEG_INF;
            }
        }
    }

    // ---- far offsets from global (clamped loads, uniform shuffles) ----
    #pragma unroll
    for (int jf = 0; jf < 3; ++jf) {
        const int d = (jf == 0) ? 256 : ((jf == 1) ? 512 : 1024);
        const int j = 17 + jf;
        #pragma unroll
        for (int p = 0; p < PPG; ++p) {
            const bool valid = (n + p) >= d;
            const int idx = valid ? (n + p - d) : 0;
            const float* kr = k + base + idx * HD;
            const ulonglong2 K0 = *(const ulonglong2*)(kr + c0);
            const ulonglong2 K1 = *(const ulonglong2*)(kr + c1);
            float t = bfly8(dot8(Q0[p], Q1[p], K0, K1));
            s[p][j] = valid ? fmaf(t, 0.125f, s[p][j]) : NEG_INF;
        }
    }

    // ---- softmax (unnormalized weights; normalize at store) ----
    float inv[PPG];
    #pragma unroll
    for (int p = 0; p < PPG; ++p) {
        float m = s[p][0];
        #pragma unroll
        for (int j = 1; j < NJ; ++j) m = fmaxf(m, s[p][j]);
        if ((n + p) == 0) m = 0.f;
        float den = 0.f;
        #pragma unroll
        for (int j = 0; j < NJ; ++j) {
            s[p][j] = __expf(s[p][j] - m);
            den += s[p][j];
        }
        inv[p] = __frcp_rn(fmaxf(den, 1e-30f));
    }

    // ---- pass 2: weighted V with the same row reuse ----
    ulonglong2 A0[PPG], A1[PPG];
    #pragma unroll
    for (int p = 0; p < PPG; ++p) {
        A0[p].x = A0[p].y = A1[p].x = A1[p].y = 0ull;
    }

    #pragma unroll
    for (int ei = 0; ei < NE; ++ei) {
        const int e = erow(ei);
        const float* vr = sv + (liBase - e) * HD;
        const ulonglong2 V0 = *(const ulonglong2*)(vr + c0);
        const ulonglong2 V1 = *(const ulonglong2*)(vr + c1);
        #pragma unroll
        for (int p = 0; p < PPG; ++p) {
            const int j = jof(e + p);
            if (j >= 0) {
                const float w = s[p][j];   // masked positions carry w=0
                const ull w2 = pk2(w, w);
                A0[p].x = f2fma(w2, V0.x, A0[p].x);
                A0[p].y = f2fma(w2, V0.y, A0[p].y);
                A1[p].x = f2fma(w2, V1.x, A1[p].x);
                A1[p].y = f2fma(w2, V1.y, A1[p].y);
            }
        }
    }

    #pragma unroll
    for (int jf = 0; jf < 3; ++jf) {
        const int d = (jf == 0) ? 256 : ((jf == 1) ? 512 : 1024);
        const int j = 17 + jf;
        #pragma unroll
        for (int p = 0; p < PPG; ++p) {
            const bool valid = (n + p) >= d;
            const int idx = valid ? (n + p - d) : 0;
            const float* vr = v + base + idx * HD;
            const ulonglong2 V0 = *(const ulonglong2*)(vr + c0);
            const ulonglong2 V1 = *(const ulonglong2*)(vr + c1);
            const float w = valid ? s[p][j] : 0.f;
            const ull w2 = pk2(w, w);
            A0[p].x = f2fma(w2, V0.x, A0[p].x);
            A0[p].y = f2fma(w2, V0.y, A0[p].y);
            A1[p].x = f2fma(w2, V1.x, A1[p].x);
            A1[p].y = f2fma(w2, V1.y, A1[p].y);
        }
    }

    // ---- normalize + store ----
    #pragma unroll
    for (int p = 0; p < PPG; ++p) {
        const ull iv2 = pk2(inv[p], inv[p]);
        ulonglong2 R0, R1;
        R0.x = f2mul(A0[p].x, iv2);
        R0.y = f2mul(A0[p].y, iv2);
        R1.x = f2mul(A1[p].x, iv2);
        R1.y = f2mul(A1[p].y, iv2);
        float* outr = out + base + (n + p) * HD;
        *(ulonglong2*)(outr + c0) = R0;
        *(ulonglong2*)(outr + c1) = R1;
    }
}

extern "C" void kernel_launch(void* const* d_in, const int* in_sizes, int n_in,
                              void* d_out, int out_size)
{
    const float* q  = (const float*)d_in[0];
    const float* k  = (const float*)d_in[1];
    const float* v  = (const float*)d_in[2];
    const float* pb = (const float*)d_in[3];
    const float* se = (const float*)d_in[4];
    float* out = (float*)d_out;

    cudaMemcpyToSymbolAsync(c_se, se, NJ * HD * sizeof(float), 0,
                            cudaMemcpyDeviceToDevice);
    cudaMemcpyToSymbolAsync(c_pb, pb, NJ * HQ * sizeof(float), 0,
                            cudaMemcpyDeviceToDevice);

    cudaFuncSetAttribute(dsqg_pre_kernel,
                         cudaFuncAttributeMaxDynamicSharedMemorySize, PRE_SMEM_BYTES);
    cudaFuncSetAttribute(dsqg_attn_kernel,
                         cudaFuncAttributeMaxDynamicSharedMemorySize, SMEM_BYTES);

    dim3 gridA(NQ / PRE_TILE, BQ * HQ);
    dsqg_pre_kernel<<<gridA, PRE_THREADS, PRE_SMEM_BYTES>>>(q);

    dim3 gridB(NQ / TILE, BQ * HQ);
    dsqg_attn_kernel<<<gridB, 1024, SMEM_BYTES>>>(q, k, v, out);
}